// round 1
// baseline (speedup 1.0000x reference)
#include <cuda_runtime.h>
#include <math.h>

#define N_NODES 50000
#define N_EDGES 800000
#define HID 96
#define HEADS 4
#define HD 24
#define NEG_SLOPE 0.2f

// ---------------- scratch (no allocations allowed) ----------------
__device__ float g_feat[N_NODES * HID];   // h @ W for current layer
__device__ float g_h0[N_NODES * HID];     // layer output ping
__device__ float g_h1[N_NODES * HID];     // layer output pong
__device__ float g_el[N_NODES * HEADS];
__device__ float g_er[N_NODES * HEADS];
__device__ float g_w[N_EDGES * HEADS];    // per-sorted-edge exp weights
__device__ int   g_row_off[N_NODES + 1];
__device__ int   g_wptr[N_NODES];         // also used as counts
__device__ int   g_csr_src[N_EDGES];
__device__ int   g_bsum[64];

// ---------------- CSR build ----------------
__global__ void zero_int_kernel(int* p, int n) {
    int i = blockIdx.x * blockDim.x + threadIdx.x;
    if (i < n) p[i] = 0;
}

__global__ void count_kernel(const int* __restrict__ dst, int* __restrict__ counts) {
    int e = blockIdx.x * blockDim.x + threadIdx.x;
    if (e < N_EDGES) atomicAdd(&counts[dst[e]], 1);
}

// block-level exclusive scan (writes exclusive partial into out, block sum into bsum)
__global__ void scan1_kernel(const int* __restrict__ in, int* __restrict__ out,
                             int* __restrict__ bsum, int n) {
    __shared__ int sh[1024];
    int i = blockIdx.x * 1024 + threadIdx.x;
    int v = (i < n) ? in[i] : 0;
    sh[threadIdx.x] = v;
    __syncthreads();
    for (int off = 1; off < 1024; off <<= 1) {
        int t = (threadIdx.x >= off) ? sh[threadIdx.x - off] : 0;
        __syncthreads();
        sh[threadIdx.x] += t;
        __syncthreads();
    }
    if (i < n) out[i] = sh[threadIdx.x] - v;   // exclusive
    if (threadIdx.x == 1023) bsum[blockIdx.x] = sh[1023];
}

__global__ void scan2_kernel(int* bsum, int nb) {
    if (threadIdx.x == 0 && blockIdx.x == 0) {
        int run = 0;
        for (int i = 0; i < nb; i++) { int v = bsum[i]; bsum[i] = run; run += v; }
    }
}

__global__ void scan3_kernel(int* __restrict__ out, const int* __restrict__ bsum, int n, int total) {
    int i = blockIdx.x * 1024 + threadIdx.x;
    if (i < n) out[i] += bsum[i >> 10];
    if (i == 0) out[n] = total;
}

__global__ void copy_int_kernel(int* __restrict__ to, const int* __restrict__ from, int n) {
    int i = blockIdx.x * blockDim.x + threadIdx.x;
    if (i < n) to[i] = from[i];
}

__global__ void scatter_kernel(const int* __restrict__ src, const int* __restrict__ dst,
                               int* __restrict__ wptr, int* __restrict__ csr_src) {
    int e = blockIdx.x * blockDim.x + threadIdx.x;
    if (e < N_EDGES) {
        int p = atomicAdd(&wptr[dst[e]], 1);
        csr_src[p] = src[e];
    }
}

// ---------------- GEMM: C[n,96] = A[n,K] @ W[K,96] ----------------
// block: 32 rows x 96 cols, blockDim (32,8), micro-tile 4x3 per thread
__global__ void gemm_kernel(const float* __restrict__ A, const float* __restrict__ W,
                            float* __restrict__ C, int n, int K) {
    __shared__ float As[32][33];
    __shared__ float Bs[32][96];
    int tx = threadIdx.x, ty = threadIdx.y;
    int tid = ty * 32 + tx;
    int row0 = blockIdx.x * 32;
    float acc[4][3] = {};
    for (int k0 = 0; k0 < K; k0 += 32) {
        #pragma unroll
        for (int t = 0; t < 4; t++) {
            int idx = tid + t * 256;
            int r = idx >> 5, k = idx & 31;
            As[r][k] = (row0 + r < n) ? A[(size_t)(row0 + r) * K + k0 + k] : 0.f;
        }
        #pragma unroll
        for (int t = 0; t < 12; t++) {
            int idx = tid + t * 256;
            int k = idx / 96, c = idx - k * 96;
            Bs[k][c] = W[(size_t)(k0 + k) * 96 + c];
        }
        __syncthreads();
        #pragma unroll
        for (int kk = 0; kk < 32; kk++) {
            float b0 = Bs[kk][tx], b1 = Bs[kk][tx + 32], b2 = Bs[kk][tx + 64];
            #pragma unroll
            for (int i = 0; i < 4; i++) {
                float a = As[ty * 4 + i][kk];
                acc[i][0] += a * b0;
                acc[i][1] += a * b1;
                acc[i][2] += a * b2;
            }
        }
        __syncthreads();
    }
    #pragma unroll
    for (int i = 0; i < 4; i++) {
        int r = row0 + ty * 4 + i;
        if (r < n) {
            C[(size_t)r * 96 + tx]      = acc[i][0];
            C[(size_t)r * 96 + tx + 32] = acc[i][1];
            C[(size_t)r * 96 + tx + 64] = acc[i][2];
        }
    }
}

// ---------------- per-node attention coefficients ----------------
__global__ void attn_coef_kernel(const float* __restrict__ feat,
                                 const float* __restrict__ al, const float* __restrict__ ar,
                                 float* __restrict__ el, float* __restrict__ er) {
    int i = blockIdx.x * blockDim.x + threadIdx.x;
    if (i >= N_NODES * HEADS) return;
    int node = i >> 2, h = i & 3;
    const float* f = feat + (size_t)node * HID + h * HD;
    float sl = 0.f, sr = 0.f;
    #pragma unroll
    for (int d = 0; d < HD; d++) {
        float v = f[d];
        sl += v * al[h * HD + d];
        sr += v * ar[h * HD + d];
    }
    el[i] = sl;
    er[i] = sr;
}

// ---------------- aggregation: warp per node ----------------
__global__ void aggregate_kernel(const float* __restrict__ feat,
                                 const int* __restrict__ row_off,
                                 const int* __restrict__ csr_src,
                                 const float* __restrict__ el,
                                 const float* __restrict__ er,
                                 const float* __restrict__ bias,
                                 float* __restrict__ wbuf,
                                 float* __restrict__ out) {
    int warp = (blockIdx.x * blockDim.x + threadIdx.x) >> 5;
    int lane = threadIdx.x & 31;
    if (warp >= N_NODES) return;
    int node = warp;
    int beg = row_off[node], end = row_off[node + 1];

    float ern[4];
    #pragma unroll
    for (int h = 0; h < 4; h++) ern[h] = er[node * 4 + h];

    // pass 1: per-head max (lane-parallel over edges)
    float m[4] = {-1e30f, -1e30f, -1e30f, -1e30f};
    for (int i = beg + lane; i < end; i += 32) {
        int s = csr_src[i];
        #pragma unroll
        for (int h = 0; h < 4; h++) {
            float e = el[s * 4 + h] + ern[h];
            e = e > 0.f ? e : NEG_SLOPE * e;
            m[h] = fmaxf(m[h], e);
        }
    }
    #pragma unroll
    for (int off = 16; off; off >>= 1)
        #pragma unroll
        for (int h = 0; h < 4; h++)
            m[h] = fmaxf(m[h], __shfl_xor_sync(0xffffffffu, m[h], off));

    // pass 1b: exp weights + denom (lane-parallel)
    float den[4] = {0.f, 0.f, 0.f, 0.f};
    for (int i = beg + lane; i < end; i += 32) {
        int s = csr_src[i];
        float4 w;
        float e0 = el[s * 4 + 0] + ern[0]; e0 = e0 > 0.f ? e0 : NEG_SLOPE * e0;
        float e1 = el[s * 4 + 1] + ern[1]; e1 = e1 > 0.f ? e1 : NEG_SLOPE * e1;
        float e2 = el[s * 4 + 2] + ern[2]; e2 = e2 > 0.f ? e2 : NEG_SLOPE * e2;
        float e3 = el[s * 4 + 3] + ern[3]; e3 = e3 > 0.f ? e3 : NEG_SLOPE * e3;
        w.x = __expf(e0 - m[0]); den[0] += w.x;
        w.y = __expf(e1 - m[1]); den[1] += w.y;
        w.z = __expf(e2 - m[2]); den[2] += w.z;
        w.w = __expf(e3 - m[3]); den[3] += w.w;
        *(float4*)&wbuf[(size_t)i * 4] = w;
    }
    #pragma unroll
    for (int off = 16; off; off >>= 1)
        #pragma unroll
        for (int h = 0; h < 4; h++)
            den[h] += __shfl_xor_sync(0xffffffffu, den[h], off);

    // pass 2: accumulate unnormalized messages (warp-cooperative over 96 feats)
    float acc0 = 0.f, acc1 = 0.f, acc2 = 0.f;
    for (int i = beg; i < end; i++) {
        int s = csr_src[i];                                  // broadcast
        float4 w = *(const float4*)&wbuf[(size_t)i * 4];     // broadcast
        const float* fs = feat + (size_t)s * 96;
        float wA = (lane < 24) ? w.x : w.y;   // head of feature 'lane'
        float wB = (lane < 16) ? w.y : w.z;   // head of feature 'lane+32'
        float wC = (lane < 8)  ? w.z : w.w;   // head of feature 'lane+64'
        acc0 += wA * fs[lane];
        acc1 += wB * fs[lane + 32];
        acc2 += wC * fs[lane + 64];
    }

    // epilogue: normalize + bias + ELU
    float inv[4];
    #pragma unroll
    for (int h = 0; h < 4; h++) inv[h] = (end > beg) ? (1.f / den[h]) : 0.f;
    float iA = (lane < 24) ? inv[0] : inv[1];
    float iB = (lane < 16) ? inv[1] : inv[2];
    float iC = (lane < 8)  ? inv[2] : inv[3];

    float v0 = acc0 * iA + bias[lane];
    float v1 = acc1 * iB + bias[lane + 32];
    float v2 = acc2 * iC + bias[lane + 64];
    v0 = v0 > 0.f ? v0 : expm1f(v0);
    v1 = v1 > 0.f ? v1 : expm1f(v1);
    v2 = v2 > 0.f ? v2 : expm1f(v2);
    out[(size_t)node * 96 + lane]      = v0;
    out[(size_t)node * 96 + lane + 32] = v1;
    out[(size_t)node * 96 + lane + 64] = v2;
}

// ---------------- final mean pool ----------------
__global__ void zero_out_kernel(float* out) {
    if (threadIdx.x < 96) out[threadIdx.x] = 0.f;
}

__global__ void mean_kernel(const float* __restrict__ h, float* __restrict__ out) {
    int c = threadIdx.x;          // 0..95
    int b = blockIdx.x;           // 0..63
    float s = 0.f;
    for (int r = b; r < N_NODES; r += gridDim.x) s += h[(size_t)r * 96 + c];
    atomicAdd(&out[c], s * (1.f / N_NODES));
}

// ---------------- launch ----------------
extern "C" void kernel_launch(void* const* d_in, const int* in_sizes, int n_in,
                              void* d_out, int out_size) {
    const float* feats = (const float*)d_in[0];
    const int*   src   = (const int*)d_in[1];
    const int*   dst   = (const int*)d_in[2];
    const float* W[3]  = {(const float*)d_in[3],  (const float*)d_in[7],  (const float*)d_in[11]};
    const float* al[3] = {(const float*)d_in[4],  (const float*)d_in[8],  (const float*)d_in[12]};
    const float* ar[3] = {(const float*)d_in[5],  (const float*)d_in[9],  (const float*)d_in[13]};
    const float* bb[3] = {(const float*)d_in[6],  (const float*)d_in[10], (const float*)d_in[14]};

    float *feat, *h0, *h1, *el, *er, *wb;
    int *row_off, *wptr, *csr, *bsum;
    cudaGetSymbolAddress((void**)&feat,    g_feat);
    cudaGetSymbolAddress((void**)&h0,      g_h0);
    cudaGetSymbolAddress((void**)&h1,      g_h1);
    cudaGetSymbolAddress((void**)&el,      g_el);
    cudaGetSymbolAddress((void**)&er,      g_er);
    cudaGetSymbolAddress((void**)&wb,      g_w);
    cudaGetSymbolAddress((void**)&row_off, g_row_off);
    cudaGetSymbolAddress((void**)&wptr,    g_wptr);
    cudaGetSymbolAddress((void**)&csr,     g_csr_src);
    cudaGetSymbolAddress((void**)&bsum,    g_bsum);

    const int SB = 49;  // ceil(50000/1024)

    // --- CSR build (once; edges identical across layers) ---
    zero_int_kernel<<<(N_NODES + 255) / 256, 256>>>(wptr, N_NODES);
    count_kernel<<<(N_EDGES + 255) / 256, 256>>>(dst, wptr);
    scan1_kernel<<<SB, 1024>>>(wptr, row_off, bsum, N_NODES);
    scan2_kernel<<<1, 32>>>(bsum, SB);
    scan3_kernel<<<SB, 1024>>>(row_off, bsum, N_NODES, N_EDGES);
    copy_int_kernel<<<(N_NODES + 255) / 256, 256>>>(wptr, row_off, N_NODES);
    scatter_kernel<<<(N_EDGES + 255) / 256, 256>>>(src, dst, wptr, csr);

    // --- 3 GAT layers ---
    const float* hin = feats;
    int K = 128;
    float* houts[3] = {h0, h1, h0};
    dim3 gemm_block(32, 8);
    int gemm_grid = (N_NODES + 31) / 32;
    for (int l = 0; l < 3; l++) {
        gemm_kernel<<<gemm_grid, gemm_block>>>(hin, W[l], feat, N_NODES, K);
        attn_coef_kernel<<<(N_NODES * HEADS + 255) / 256, 256>>>(feat, al[l], ar[l], el, er);
        aggregate_kernel<<<(N_NODES * 32 + 255) / 256, 256>>>(feat, row_off, csr, el, er,
                                                              bb[l], wb, houts[l]);
        hin = houts[l];
        K = 96;
    }

    // --- mean pool ---
    zero_out_kernel<<<1, 96>>>((float*)d_out);
    mean_kernel<<<64, 96>>>(hin, (float*)d_out);
}